// round 10
// baseline (speedup 1.0000x reference)
#include <cuda_runtime.h>
#include <cstdint>

// GptOssExperts: out[t,h] = sum_e r[t,e]*(act(hs@gup[e]+gub[e])@dp[e]+dpb[e])
// Legacy mma.sync tf32 path (tcgen05 rejected by toolchain's sm_103 base target).
//  R9: R7 compute structure (256 thr / 8 warps of 64x64, ldmatrix.x4 A frags,
//      in-register frag double-buffering, pre-rounded tf32 operands) with BK=64
//      slabs + 2-stage cp.async (217KB smem) to halve per-k-step join/restart cost.

constexpr int T_DIM = 2048, H_DIM = 2048, I_DIM = 2048, E_NUM = 8;
constexpr int GU_COLS = 4096;          // 2*I
constexpr int KQ = E_NUM * I_DIM;      // 16384
constexpr int BM = 128, BN = 256, BK = 64;
constexpr int NTHR = 256;
constexpr int STAGES = 2;

constexpr int A_ROW = 272;             // 64 floats + 16B pad (16B-mult for LDSM; bank+4/row)
constexpr int B_ROW = 1056;            // 256 floats + 32B pad (bank+8/k-row)
constexpr int A_ST = BM * A_ROW;       // 34816
constexpr int B_ST = BK * B_ROW;       // 67584
constexpr int OFF_A = 0;
constexpr int OFF_B = STAGES * A_ST;             // 69632
constexpr int OFF_AUX = OFF_B + STAGES * B_ST;   // 204800
constexpr int SMEM_SZ = OFF_AUX + 12544;         // 217344

// static scratch (device-global; allocation-free)
__device__ float g_w1[67108864];       // tf32-rounded gate_up_proj  (268 MB)
__device__ float g_w2[33554432];       // tf32-rounded down_proj     (134 MB)
__device__ float g_hs[4194304];        // tf32-rounded hidden_states (16 MB)
__device__ float g_inter[33554432];    // routed-scaled intermediate [T][E*I], tf32-rounded

__device__ __forceinline__ uint32_t f2tf32(float x) {
    uint32_t r; asm("cvt.rna.tf32.f32 %0, %1;" : "=r"(r) : "f"(x)); return r;
}
__device__ __forceinline__ uint32_t cvta_smem(const void* p) {
    uint32_t a;
    asm("{ .reg .u64 t; cvta.to.shared.u64 t, %1; cvt.u32.u64 %0, t; }" : "=r"(a) : "l"(p));
    return a;
}
__device__ __forceinline__ void cp16(uint32_t saddr, const void* g) {
    asm volatile("cp.async.cg.shared.global [%0], [%1], 16;" :: "r"(saddr), "l"(g));
}
__device__ __forceinline__ void cp_commit() {
    asm volatile("cp.async.commit_group;" ::);
}
template <int N> __device__ __forceinline__ void cp_wait() {
    asm volatile("cp.async.wait_group %0;" :: "n"(N));
}
__device__ __forceinline__ void mma_tf32(float (&c)[4],
    uint32_t a0, uint32_t a1, uint32_t a2, uint32_t a3, uint32_t b0, uint32_t b1)
{
    asm volatile(
        "mma.sync.aligned.m16n8k8.row.col.f32.tf32.tf32.f32 "
        "{%0,%1,%2,%3}, {%4,%5,%6,%7}, {%8,%9}, {%0,%1,%2,%3};"
        : "+f"(c[0]), "+f"(c[1]), "+f"(c[2]), "+f"(c[3])
        : "r"(a0), "r"(a1), "r"(a2), "r"(a3), "r"(b0), "r"(b1));
}
// ldmatrix.x4 on b16 rows == tf32 m16n8k8 A fragment (validated R7)
__device__ __forceinline__ void ldsm4(uint32_t (&r)[4], uint32_t addr) {
    asm volatile("ldmatrix.sync.aligned.m8n8.x4.shared.b16 {%0,%1,%2,%3}, [%4];"
                 : "=r"(r[0]), "=r"(r[1]), "=r"(r[2]), "=r"(r[3]) : "r"(addr));
}

// ---- pre-pass: round fp32 -> tf32-representable fp32 (vectorized) ----
__global__ __launch_bounds__(256) void k_conv(const float4* __restrict__ src,
                                              float4* __restrict__ dst, int n4)
{
    int i = blockIdx.x * 256 + threadIdx.x;
    if (i < n4) {
        float4 v = src[i];
        float4 o;
        o.x = __uint_as_float(f2tf32(v.x));
        o.y = __uint_as_float(f2tf32(v.y));
        o.z = __uint_as_float(f2tf32(v.z));
        o.w = __uint_as_float(f2tf32(v.w));
        dst[i] = o;
    }
}

// ---- fragment load for one k8-step s (0..7) ----
__device__ __forceinline__ void load_frags(uint32_t sA, const char* sB,
    int s, int wc, int g, int t4, uint32_t (&a)[4][4], uint32_t (&b)[8][2])
{
#pragma unroll
    for (int mf = 0; mf < 4; mf++)
        ldsm4(a[mf], sA + mf * 16 * A_ROW + s * 32);
    const char* pb = sB + (s * 8 + t4) * B_ROW + (wc * 64 + g) * 4;
#pragma unroll
    for (int nf = 0; nf < 8; nf++) {
        b[nf][0] = *(const uint32_t*)(pb + nf * 32);
        b[nf][1] = *(const uint32_t*)(pb + nf * 32 + 4 * B_ROW);
    }
}
__device__ __forceinline__ void mma_step(const uint32_t (&a)[4][4],
    const uint32_t (&b)[8][2], float (&acc)[4][8][4])
{
#pragma unroll
    for (int mf = 0; mf < 4; mf++)
#pragma unroll
        for (int nf = 0; nf < 8; nf++)
            mma_tf32(acc[mf][nf], a[mf][0], a[mf][1], a[mf][2], a[mf][3],
                     b[nf][0], b[nf][1]);
}

// ---- one BK=64 slab: 8 k8-steps, in-register double-buffered fragments ----
__device__ __forceinline__ void compute_slab(uint32_t sA, const char* sB,
    int wc, int g, int t4, float (&acc)[4][8][4])
{
    uint32_t a0[4][4], b0[8][2], a1[4][4], b1[8][2];
    load_frags(sA, sB, 0, wc, g, t4, a0, b0);
    load_frags(sA, sB, 1, wc, g, t4, a1, b1);
#pragma unroll
    for (int s = 0; s < 6; s += 2) {
        mma_step(a0, b0, acc);
        load_frags(sA, sB, s + 2, wc, g, t4, a0, b0);
        mma_step(a1, b1, acc);
        load_frags(sA, sB, s + 3, wc, g, t4, a1, b1);
    }
    mma_step(a0, b0, acc);
    mma_step(a1, b1, acc);
}

// ---- cp.async copy of one BK=64 slab (256 threads; 24 x 16B per thread) ----
struct Copier { const float *ga0, *gb0; uint32_t sa0, sb0; int lda, ldb; };
__device__ __forceinline__ void init_copier(Copier& c, uint32_t smem_u32,
    const float* __restrict__ A, int lda, const float* __restrict__ B, int ldb)
{
    const int tid = threadIdx.x;
    c.lda = lda; c.ldb = ldb;
    int m = tid >> 4, kq = tid & 15;           // A chunk j: rows m + 16j, 16 chunks/row
    c.sa0 = smem_u32 + OFF_A + m * A_ROW + kq * 16;
    c.ga0 = A + (size_t)m * lda + kq * 4;
    int k = tid >> 6, nq = tid & 63;           // B chunk j: k-rows k + 4j
    c.sb0 = smem_u32 + OFF_B + k * B_ROW + nq * 16;
    c.gb0 = B + (size_t)k * ldb + nq * 4;
}
__device__ __forceinline__ void issue_slab(const Copier& c, int i) {
    const int slot = i & 1;
    const size_t ka = (size_t)i * BK;
#pragma unroll
    for (int j = 0; j < 8; j++)                // A: 2048 chunks / 256 thr
        cp16(c.sa0 + slot * A_ST + j * 16 * A_ROW, c.ga0 + ka + (size_t)j * 16 * c.lda);
#pragma unroll
    for (int j = 0; j < 16; j++)               // B: 4096 chunks / 256 thr
        cp16(c.sb0 + slot * B_ST + j * 4 * B_ROW, c.gb0 + (ka + 4 * j) * (size_t)c.ldb);
}

__device__ __forceinline__ void run_gemm(
    const float* __restrict__ A, int lda, const float* __restrict__ B, int ldb,
    int nslab, char* smem, uint32_t smem_u32, float (&acc)[4][8][4])
{
    const int tid = threadIdx.x, lane = tid & 31, wid = tid >> 5;
    const int wr = wid >> 2, wc = wid & 3, g = lane >> 2, t4 = lane & 3;

    const uint32_t sA_lane0 = smem_u32 + OFF_A
        + (uint32_t)(wr * 64 + (lane & 7) + 8 * ((lane >> 3) & 1)) * A_ROW
        + (uint32_t)(lane >> 4) * 16;

    Copier c; init_copier(c, smem_u32, A, lda, B, ldb);

    issue_slab(c, 0); cp_commit();
    issue_slab(c, 1); cp_commit();
    cp_wait<1>();                 // slab 0 retired (own copies)
    __syncthreads();              // slab 0 visible to all

    for (int i = 0; i < nslab; i++) {
        const int slot = i & 1;
        compute_slab(sA_lane0 + slot * A_ST, smem + OFF_B + slot * B_ST,
                     wc, g, t4, acc);
        __syncthreads();          // all warps done reading slot(i) before overwrite
        if (i + 2 < nslab) issue_slab(c, i + 2);
        cp_commit();
        cp_wait<1>();             // slab i+1 (issued last iter) retired (own copies)
        __syncthreads();          // slab i+1 visible to all
    }
}

// ================= Stage 1: gu = hs @ gup[e] + gub; GLU; fold routing -> g_inter =================
__global__ __launch_bounds__(NTHR, 1) void k_gemm1(
    const float* __restrict__ routing, const float* __restrict__ gub)
{
    extern __shared__ char smem[];
    const uint32_t sb = cvta_smem(smem);
    const int tid = threadIdx.x, lane = tid & 31, wid = tid >> 5;
    const int wr = wid >> 2, wc = wid & 3, g = lane >> 2, t4 = lane & 3;
    const int e = blockIdx.z, t0 = blockIdx.y * BM, j0 = blockIdx.x * BN;

    float* rs   = (float*)(smem + OFF_AUX);        // [128]
    float* bias = (float*)(smem + OFF_AUX + 512);  // [256]
    if (tid < 128) rs[tid] = routing[(size_t)(t0 + tid) * E_NUM + e];
    bias[tid] = gub[(size_t)e * GU_COLS + j0 + tid];
    __syncthreads();

    float acc[4][8][4] = {};
    run_gemm(g_hs + (size_t)t0 * H_DIM, H_DIM,
             g_w1 + (size_t)e * H_DIM * GU_COLS + j0, GU_COLS,
             H_DIM / BK, smem, sb, acc);

#pragma unroll
    for (int mf = 0; mf < 4; mf++) {
#pragma unroll
        for (int hi = 0; hi < 2; hi++) {
            const int r = wr * 64 + mf * 16 + g + hi * 8;
            const float rv = rs[r];
            float* grow = g_inter + (size_t)(t0 + r) * KQ + (size_t)e * I_DIM + (j0 >> 1);
#pragma unroll
            for (int nf = 0; nf < 8; nf++) {
                const int cn = wc * 64 + nf * 8 + 2 * t4;  // even gu col = gate; +1 = up
                float gate = acc[mf][nf][hi * 2]     + bias[cn];
                float up   = acc[mf][nf][hi * 2 + 1] + bias[cn + 1];
                gate = fminf(gate, 7.0f);
                up   = fminf(fmaxf(up, -7.0f), 7.0f);
                const float glu = gate / (1.0f + __expf(-1.702f * gate));
                grow[cn >> 1] = __uint_as_float(f2tf32((up + 1.0f) * glu * rv));
            }
        }
    }
}

// ================= Stage 2: out = inter'[T,E*I] @ down[E*I,H] + routing @ dpb =================
__global__ __launch_bounds__(NTHR, 1) void k_gemm2(
    const float* __restrict__ routing, const float* __restrict__ dpb,
    float* __restrict__ out)
{
    extern __shared__ char smem[];
    const uint32_t sb = cvta_smem(smem);
    const int tid = threadIdx.x, lane = tid & 31, wid = tid >> 5;
    const int wr = wid >> 2, wc = wid & 3, g = lane >> 2, t4 = lane & 3;
    const int t0 = blockIdx.y * BM, h0 = blockIdx.x * BN;

    float* rsm = (float*)(smem + OFF_AUX);         // [128][8]
    float* dsm = (float*)(smem + OFF_AUX + 4096);  // [8][256]
#pragma unroll
    for (int j = 0; j < 4; j++) {
        int idx = tid + NTHR * j;
        rsm[idx] = routing[(size_t)t0 * E_NUM + idx];
    }
#pragma unroll
    for (int j = 0; j < 8; j++) {
        int idx = tid + NTHR * j;
        dsm[idx] = dpb[(size_t)(idx >> 8) * H_DIM + h0 + (idx & 255)];
    }
    __syncthreads();

    float acc[4][8][4] = {};
    run_gemm(g_inter + (size_t)t0 * KQ, KQ,
             g_w2 + h0, H_DIM,
             KQ / BK, smem, sb, acc);

#pragma unroll
    for (int nf = 0; nf < 8; nf++) {
        const int cn = wc * 64 + nf * 8 + 2 * t4;
        float d0[8], d1[8];
#pragma unroll
        for (int e2 = 0; e2 < 8; e2++) {
            d0[e2] = dsm[e2 * 256 + cn];
            d1[e2] = dsm[e2 * 256 + cn + 1];
        }
#pragma unroll
        for (int mf = 0; mf < 4; mf++) {
#pragma unroll
            for (int hi = 0; hi < 2; hi++) {
                const int r = wr * 64 + mf * 16 + g + hi * 8;
                const float4* rp = (const float4*)(rsm + r * 8);
                const float4 rA = rp[0], rB = rp[1];
                float b0 = rA.x * d0[0] + rA.y * d0[1] + rA.z * d0[2] + rA.w * d0[3]
                         + rB.x * d0[4] + rB.y * d0[5] + rB.z * d0[6] + rB.w * d0[7];
                float b1 = rA.x * d1[0] + rA.y * d1[1] + rA.z * d1[2] + rA.w * d1[3]
                         + rB.x * d1[4] + rB.y * d1[5] + rB.z * d1[6] + rB.w * d1[7];
                float2 v;
                v.x = acc[mf][nf][hi * 2]     + b0;
                v.y = acc[mf][nf][hi * 2 + 1] + b1;
                *(float2*)(out + (size_t)(t0 + r) * H_DIM + h0 + cn) = v;
            }
        }
    }
}

extern "C" void kernel_launch(void* const* d_in, const int* in_sizes, int n_in,
                              void* d_out, int out_size)
{
    const float* hidden  = (const float*)d_in[0];
    const float* routing = (const float*)d_in[1];
    const float* gup     = (const float*)d_in[2];
    const float* gub     = (const float*)d_in[3];
    const float* down    = (const float*)d_in[4];
    const float* dpb     = (const float*)d_in[5];
    float* out = (float*)d_out;

    cudaFuncSetAttribute(k_gemm1, cudaFuncAttributeMaxDynamicSharedMemorySize, SMEM_SZ);
    cudaFuncSetAttribute(k_gemm2, cudaFuncAttributeMaxDynamicSharedMemorySize, SMEM_SZ);

    float *w1, *w2, *hs;
    cudaGetSymbolAddress((void**)&w1, g_w1);
    cudaGetSymbolAddress((void**)&w2, g_w2);
    cudaGetSymbolAddress((void**)&hs, g_hs);

    // pre-round all GEMM operands to tf32-representable fp32 (removes in-loop CVT)
    k_conv<<<(16777216 + 255) / 256, 256>>>((const float4*)gup,    (float4*)w1, 16777216);
    k_conv<<<( 8388608 + 255) / 256, 256>>>((const float4*)down,   (float4*)w2,  8388608);
    k_conv<<<( 1048576 + 255) / 256, 256>>>((const float4*)hidden, (float4*)hs,  1048576);

    dim3 g1(GU_COLS / BN, T_DIM / BM, E_NUM);   // (16, 16, 8)
    k_gemm1<<<g1, NTHR, SMEM_SZ>>>(routing, gub);

    dim3 g2(H_DIM / BN, T_DIM / BM);            // (8, 16)
    k_gemm2<<<g2, NTHR, SMEM_SZ>>>(routing, dpb, out);
}

// round 11
// speedup vs baseline: 1.0494x; 1.0494x over previous
#include <cuda_runtime.h>
#include <cstdint>

// GptOssExperts: out[t,h] = sum_e r[t,e]*(act(hs@gup[e]+gub[e])@dp[e]+dpb[e])
// Legacy mma.sync tf32 path (tcgen05 rejected by toolchain's sm_103 base target).
//  R11: R9 (BK=64, 2-stage cp.async, 8 warps of 64x64, ldmatrix.x4 A frags, pre-rounded
//       tf32 operands) + barrier/copy-issue moved INSIDE the slab: all slot-i reads end
//       two mma_steps early, so the LDGSTS burst + barrier + cp_wait hide under 1024 cyc
//       of queued MMA. No fragment state added across the barrier (R8 lesson).

constexpr int T_DIM = 2048, H_DIM = 2048, I_DIM = 2048, E_NUM = 8;
constexpr int GU_COLS = 4096;          // 2*I
constexpr int KQ = E_NUM * I_DIM;      // 16384
constexpr int BM = 128, BN = 256, BK = 64;
constexpr int NTHR = 256;
constexpr int STAGES = 2;

constexpr int A_ROW = 272;             // 64 floats + 16B pad (16B-mult for LDSM; bank+4/row)
constexpr int B_ROW = 1056;            // 256 floats + 32B pad (bank+8/k-row)
constexpr int A_ST = BM * A_ROW;       // 34816
constexpr int B_ST = BK * B_ROW;       // 67584
constexpr int OFF_A = 0;
constexpr int OFF_B = STAGES * A_ST;             // 69632
constexpr int OFF_AUX = OFF_B + STAGES * B_ST;   // 204800
constexpr int SMEM_SZ = OFF_AUX + 12544;         // 217344

// static scratch (device-global; allocation-free)
__device__ float g_w1[67108864];       // tf32-rounded gate_up_proj  (268 MB)
__device__ float g_w2[33554432];       // tf32-rounded down_proj     (134 MB)
__device__ float g_hs[4194304];        // tf32-rounded hidden_states (16 MB)
__device__ float g_inter[33554432];    // routed-scaled intermediate [T][E*I], tf32-rounded

__device__ __forceinline__ uint32_t f2tf32(float x) {
    uint32_t r; asm("cvt.rna.tf32.f32 %0, %1;" : "=r"(r) : "f"(x)); return r;
}
__device__ __forceinline__ uint32_t cvta_smem(const void* p) {
    uint32_t a;
    asm("{ .reg .u64 t; cvta.to.shared.u64 t, %1; cvt.u32.u64 %0, t; }" : "=r"(a) : "l"(p));
    return a;
}
__device__ __forceinline__ void cp16(uint32_t saddr, const void* g) {
    asm volatile("cp.async.cg.shared.global [%0], [%1], 16;" :: "r"(saddr), "l"(g));
}
__device__ __forceinline__ void cp_commit() {
    asm volatile("cp.async.commit_group;" ::);
}
template <int N> __device__ __forceinline__ void cp_wait() {
    asm volatile("cp.async.wait_group %0;" :: "n"(N));
}
__device__ __forceinline__ void mma_tf32(float (&c)[4],
    uint32_t a0, uint32_t a1, uint32_t a2, uint32_t a3, uint32_t b0, uint32_t b1)
{
    asm volatile(
        "mma.sync.aligned.m16n8k8.row.col.f32.tf32.tf32.f32 "
        "{%0,%1,%2,%3}, {%4,%5,%6,%7}, {%8,%9}, {%0,%1,%2,%3};"
        : "+f"(c[0]), "+f"(c[1]), "+f"(c[2]), "+f"(c[3])
        : "r"(a0), "r"(a1), "r"(a2), "r"(a3), "r"(b0), "r"(b1));
}
// ldmatrix.x4 on b16 rows == tf32 m16n8k8 A fragment (validated R7)
__device__ __forceinline__ void ldsm4(uint32_t (&r)[4], uint32_t addr) {
    asm volatile("ldmatrix.sync.aligned.m8n8.x4.shared.b16 {%0,%1,%2,%3}, [%4];"
                 : "=r"(r[0]), "=r"(r[1]), "=r"(r[2]), "=r"(r[3]) : "r"(addr));
}

// ---- pre-pass: round fp32 -> tf32-representable fp32 (vectorized) ----
__global__ __launch_bounds__(256) void k_conv(const float4* __restrict__ src,
                                              float4* __restrict__ dst, int n4)
{
    int i = blockIdx.x * 256 + threadIdx.x;
    if (i < n4) {
        float4 v = src[i];
        float4 o;
        o.x = __uint_as_float(f2tf32(v.x));
        o.y = __uint_as_float(f2tf32(v.y));
        o.z = __uint_as_float(f2tf32(v.z));
        o.w = __uint_as_float(f2tf32(v.w));
        dst[i] = o;
    }
}

// ---- fragment load for one k8-step s (0..7) ----
__device__ __forceinline__ void load_frags(uint32_t sA, const char* sB,
    int s, int wc, int g, int t4, uint32_t (&a)[4][4], uint32_t (&b)[8][2])
{
#pragma unroll
    for (int mf = 0; mf < 4; mf++)
        ldsm4(a[mf], sA + mf * 16 * A_ROW + s * 32);
    const char* pb = sB + (s * 8 + t4) * B_ROW + (wc * 64 + g) * 4;
#pragma unroll
    for (int nf = 0; nf < 8; nf++) {
        b[nf][0] = *(const uint32_t*)(pb + nf * 32);
        b[nf][1] = *(const uint32_t*)(pb + nf * 32 + 4 * B_ROW);
    }
}
__device__ __forceinline__ void mma_step(const uint32_t (&a)[4][4],
    const uint32_t (&b)[8][2], float (&acc)[4][8][4])
{
#pragma unroll
    for (int mf = 0; mf < 4; mf++)
#pragma unroll
        for (int nf = 0; nf < 8; nf++)
            mma_tf32(acc[mf][nf], a[mf][0], a[mf][1], a[mf][2], a[mf][3],
                     b[nf][0], b[nf][1]);
}

// ---- cp.async copy of one BK=64 slab (256 threads; 24 x 16B per thread) ----
struct Copier { const float *ga0, *gb0; uint32_t sa0, sb0; int lda, ldb; };
__device__ __forceinline__ void init_copier(Copier& c, uint32_t smem_u32,
    const float* __restrict__ A, int lda, const float* __restrict__ B, int ldb)
{
    const int tid = threadIdx.x;
    c.lda = lda; c.ldb = ldb;
    int m = tid >> 4, kq = tid & 15;           // A chunk j: rows m + 16j
    c.sa0 = smem_u32 + OFF_A + m * A_ROW + kq * 16;
    c.ga0 = A + (size_t)m * lda + kq * 4;
    int k = tid >> 6, nq = tid & 63;           // B chunk j: k-rows k + 4j
    c.sb0 = smem_u32 + OFF_B + k * B_ROW + nq * 16;
    c.gb0 = B + (size_t)k * ldb + nq * 4;
}
__device__ __forceinline__ void issue_slab(const Copier& c, int i) {
    const int slot = i & 1;
    const size_t ka = (size_t)i * BK;
#pragma unroll
    for (int j = 0; j < 8; j++)                // A: 2048 chunks / 256 thr
        cp16(c.sa0 + slot * A_ST + j * 16 * A_ROW, c.ga0 + ka + (size_t)j * 16 * c.lda);
#pragma unroll
    for (int j = 0; j < 16; j++)               // B: 4096 chunks / 256 thr
        cp16(c.sb0 + slot * B_ST + j * 4 * B_ROW, c.gb0 + (ka + 4 * j) * (size_t)c.ldb);
}

__device__ __forceinline__ void run_gemm(
    const float* __restrict__ A, int lda, const float* __restrict__ B, int ldb,
    int nslab, char* smem, uint32_t smem_u32, float (&acc)[4][8][4])
{
    const int tid = threadIdx.x, lane = tid & 31, wid = tid >> 5;
    const int wr = wid >> 2, wc = wid & 3, g = lane >> 2, t4 = lane & 3;

    const uint32_t sA_lane0 = smem_u32 + OFF_A
        + (uint32_t)(wr * 64 + (lane & 7) + 8 * ((lane >> 3) & 1)) * A_ROW
        + (uint32_t)(lane >> 4) * 16;

    Copier c; init_copier(c, smem_u32, A, lda, B, ldb);

    issue_slab(c, 0); cp_commit();
    issue_slab(c, 1); cp_commit();
    cp_wait<1>();                 // slab 0 retired (own copies)
    __syncthreads();              // slab 0 visible to all

    for (int i = 0; i < nslab; i++) {
        const int slot = i & 1;
        const uint32_t sA = sA_lane0 + slot * A_ST;
        const char* sB = smem + OFF_B + slot * B_ST;

        uint32_t a0[4][4], b0[8][2], a1[4][4], b1[8][2];
        load_frags(sA, sB, 0, wc, g, t4, a0, b0);
        load_frags(sA, sB, 1, wc, g, t4, a1, b1);
#pragma unroll
        for (int s = 0; s < 6; s += 2) {
            mma_step(a0, b0, acc);
            load_frags(sA, sB, s + 2, wc, g, t4, a0, b0);
            mma_step(a1, b1, acc);
            load_frags(sA, sB, s + 3, wc, g, t4, a1, b1);
        }
        // All reads of slot(i) are issued; join and refill it under the last 2 MMA bursts.
        __syncthreads();
        if (i + 2 < nslab) issue_slab(c, i + 2);
        cp_commit();
        mma_step(a0, b0, acc);    // ~1024 cyc of queued MMA hide issue + wait + join
        mma_step(a1, b1, acc);
        cp_wait<1>();             // slab i+1 (committed last iteration) retired
        __syncthreads();          // slab i+1 visible to all
    }
}

// ================= Stage 1: gu = hs @ gup[e] + gub; GLU; fold routing -> g_inter =================
__global__ __launch_bounds__(NTHR, 1) void k_gemm1(
    const float* __restrict__ routing, const float* __restrict__ gub)
{
    extern __shared__ char smem[];
    const uint32_t sb = cvta_smem(smem);
    const int tid = threadIdx.x, lane = tid & 31, wid = tid >> 5;
    const int wr = wid >> 2, wc = wid & 3, g = lane >> 2, t4 = lane & 3;
    const int e = blockIdx.z, t0 = blockIdx.y * BM, j0 = blockIdx.x * BN;

    float* rs   = (float*)(smem + OFF_AUX);        // [128]
    float* bias = (float*)(smem + OFF_AUX + 512);  // [256]
    if (tid < 128) rs[tid] = routing[(size_t)(t0 + tid) * E_NUM + e];
    bias[tid] = gub[(size_t)e * GU_COLS + j0 + tid];
    __syncthreads();

    float acc[4][8][4] = {};
    run_gemm(g_hs + (size_t)t0 * H_DIM, H_DIM,
             g_w1 + (size_t)e * H_DIM * GU_COLS + j0, GU_COLS,
             H_DIM / BK, smem, sb, acc);

#pragma unroll
    for (int mf = 0; mf < 4; mf++) {
#pragma unroll
        for (int hi = 0; hi < 2; hi++) {
            const int r = wr * 64 + mf * 16 + g + hi * 8;
            const float rv = rs[r];
            float* grow = g_inter + (size_t)(t0 + r) * KQ + (size_t)e * I_DIM + (j0 >> 1);
#pragma unroll
            for (int nf = 0; nf < 8; nf++) {
                const int cn = wc * 64 + nf * 8 + 2 * t4;  // even gu col = gate; +1 = up
                float gate = acc[mf][nf][hi * 2]     + bias[cn];
                float up   = acc[mf][nf][hi * 2 + 1] + bias[cn + 1];
                gate = fminf(gate, 7.0f);
                up   = fminf(fmaxf(up, -7.0f), 7.0f);
                const float glu = gate / (1.0f + __expf(-1.702f * gate));
                grow[cn >> 1] = __uint_as_float(f2tf32((up + 1.0f) * glu * rv));
            }
        }
    }
}

// ================= Stage 2: out = inter'[T,E*I] @ down[E*I,H] + routing @ dpb =================
__global__ __launch_bounds__(NTHR, 1) void k_gemm2(
    const float* __restrict__ routing, const float* __restrict__ dpb,
    float* __restrict__ out)
{
    extern __shared__ char smem[];
    const uint32_t sb = cvta_smem(smem);
    const int tid = threadIdx.x, lane = tid & 31, wid = tid >> 5;
    const int wr = wid >> 2, wc = wid & 3, g = lane >> 2, t4 = lane & 3;
    const int t0 = blockIdx.y * BM, h0 = blockIdx.x * BN;

    float* rsm = (float*)(smem + OFF_AUX);         // [128][8]
    float* dsm = (float*)(smem + OFF_AUX + 4096);  // [8][256]
#pragma unroll
    for (int j = 0; j < 4; j++) {
        int idx = tid + NTHR * j;
        rsm[idx] = routing[(size_t)t0 * E_NUM + idx];
    }
#pragma unroll
    for (int j = 0; j < 8; j++) {
        int idx = tid + NTHR * j;
        dsm[idx] = dpb[(size_t)(idx >> 8) * H_DIM + h0 + (idx & 255)];
    }
    __syncthreads();

    float acc[4][8][4] = {};
    run_gemm(g_inter + (size_t)t0 * KQ, KQ,
             g_w2 + h0, H_DIM,
             KQ / BK, smem, sb, acc);

#pragma unroll
    for (int nf = 0; nf < 8; nf++) {
        const int cn = wc * 64 + nf * 8 + 2 * t4;
        float d0[8], d1[8];
#pragma unroll
        for (int e2 = 0; e2 < 8; e2++) {
            d0[e2] = dsm[e2 * 256 + cn];
            d1[e2] = dsm[e2 * 256 + cn + 1];
        }
#pragma unroll
        for (int mf = 0; mf < 4; mf++) {
#pragma unroll
            for (int hi = 0; hi < 2; hi++) {
                const int r = wr * 64 + mf * 16 + g + hi * 8;
                const float4* rp = (const float4*)(rsm + r * 8);
                const float4 rA = rp[0], rB = rp[1];
                float b0 = rA.x * d0[0] + rA.y * d0[1] + rA.z * d0[2] + rA.w * d0[3]
                         + rB.x * d0[4] + rB.y * d0[5] + rB.z * d0[6] + rB.w * d0[7];
                float b1 = rA.x * d1[0] + rA.y * d1[1] + rA.z * d1[2] + rA.w * d1[3]
                         + rB.x * d1[4] + rB.y * d1[5] + rB.z * d1[6] + rB.w * d1[7];
                float2 v;
                v.x = acc[mf][nf][hi * 2]     + b0;
                v.y = acc[mf][nf][hi * 2 + 1] + b1;
                *(float2*)(out + (size_t)(t0 + r) * H_DIM + h0 + cn) = v;
            }
        }
    }
}

extern "C" void kernel_launch(void* const* d_in, const int* in_sizes, int n_in,
                              void* d_out, int out_size)
{
    const float* hidden  = (const float*)d_in[0];
    const float* routing = (const float*)d_in[1];
    const float* gup     = (const float*)d_in[2];
    const float* gub     = (const float*)d_in[3];
    const float* down    = (const float*)d_in[4];
    const float* dpb     = (const float*)d_in[5];
    float* out = (float*)d_out;

    cudaFuncSetAttribute(k_gemm1, cudaFuncAttributeMaxDynamicSharedMemorySize, SMEM_SZ);
    cudaFuncSetAttribute(k_gemm2, cudaFuncAttributeMaxDynamicSharedMemorySize, SMEM_SZ);

    float *w1, *w2, *hs;
    cudaGetSymbolAddress((void**)&w1, g_w1);
    cudaGetSymbolAddress((void**)&w2, g_w2);
    cudaGetSymbolAddress((void**)&hs, g_hs);

    // pre-round all GEMM operands to tf32-representable fp32 (removes in-loop CVT)
    k_conv<<<(16777216 + 255) / 256, 256>>>((const float4*)gup,    (float4*)w1, 16777216);
    k_conv<<<( 8388608 + 255) / 256, 256>>>((const float4*)down,   (float4*)w2,  8388608);
    k_conv<<<( 1048576 + 255) / 256, 256>>>((const float4*)hidden, (float4*)hs,  1048576);

    dim3 g1(GU_COLS / BN, T_DIM / BM, E_NUM);   // (16, 16, 8)
    k_gemm1<<<g1, NTHR, SMEM_SZ>>>(routing, gub);

    dim3 g2(H_DIM / BN, T_DIM / BM);            // (8, 16)
    k_gemm2<<<g2, NTHR, SMEM_SZ>>>(routing, dpb, out);
}

// round 13
// speedup vs baseline: 1.0550x; 1.0053x over previous
#include <cuda_runtime.h>
#include <cstdint>

// GptOssExperts: out[t,h] = sum_e r[t,e]*(act(hs@gup[e]+gub[e])@dp[e]+dpb[e])
// Legacy mma.sync tf32 path (tcgen05 rejected by toolchain's sm_103 base target).
//  R13 = R12 with the deadlock fixed: cp.async.mbarrier.arrive NEEDS .noinc when the
//  mbarrier init count equals the thread count (default form increments pending count
//  and nets to zero -> phase never flips -> R12's hang).
//  Scheme: BK=64, 2 smem slots, 8 warps of 64x64, ldmatrix.x4 A frags, pre-rounded tf32;
//  fill[slot] mbarrier fed by cp.async.mbarrier.arrive.noinc (replaces wait_group+bar),
//  read[slot] arrived right after the last LDS of the slot, producer waits it two MMA
//  bursts later. Arrive-early/wait-late removes the per-slab convoy joins.

constexpr int T_DIM = 2048, H_DIM = 2048, I_DIM = 2048, E_NUM = 8;
constexpr int GU_COLS = 4096;          // 2*I
constexpr int KQ = E_NUM * I_DIM;      // 16384
constexpr int BM = 128, BN = 256, BK = 64;
constexpr int NTHR = 256;

constexpr int A_ROW = 272;             // 64 floats + 16B pad (16B-mult for LDSM; bank+4/row)
constexpr int B_ROW = 1056;            // 256 floats + 32B pad (bank+8/k-row)
constexpr int A_ST = BM * A_ROW;       // 34816
constexpr int B_ST = BK * B_ROW;       // 67584
constexpr int OFF_A = 0;
constexpr int OFF_B = 2 * A_ST;                  // 69632
constexpr int OFF_AUX = OFF_B + 2 * B_ST;        // 204800
constexpr int OFF_MBAR = OFF_AUX + 12288;        // 4 x 8B mbarriers
constexpr int SMEM_SZ = OFF_AUX + 12544;         // 217344

// static scratch (device-global; allocation-free)
__device__ float g_w1[67108864];       // tf32-rounded gate_up_proj  (268 MB)
__device__ float g_w2[33554432];       // tf32-rounded down_proj     (134 MB)
__device__ float g_hs[4194304];        // tf32-rounded hidden_states (16 MB)
__device__ float g_inter[33554432];    // routed-scaled intermediate [T][E*I], tf32-rounded

__device__ __forceinline__ uint32_t f2tf32(float x) {
    uint32_t r; asm("cvt.rna.tf32.f32 %0, %1;" : "=r"(r) : "f"(x)); return r;
}
__device__ __forceinline__ uint32_t cvta_smem(const void* p) {
    uint32_t a;
    asm("{ .reg .u64 t; cvta.to.shared.u64 t, %1; cvt.u32.u64 %0, t; }" : "=r"(a) : "l"(p));
    return a;
}
__device__ __forceinline__ void cp16(uint32_t saddr, const void* g) {
    asm volatile("cp.async.cg.shared.global [%0], [%1], 16;" :: "r"(saddr), "l"(g));
}
__device__ __forceinline__ void mbar_init(uint32_t addr, uint32_t cnt) {
    asm volatile("mbarrier.init.shared.b64 [%0], %1;" :: "r"(addr), "r"(cnt) : "memory");
}
__device__ __forceinline__ void mbar_arrive(uint32_t addr) {
    asm volatile("mbarrier.arrive.shared.b64 _, [%0];" :: "r"(addr) : "memory");
}
// one deferred arrival per thread when all its prior cp.asyncs complete; .noinc is
// REQUIRED for init-count==thread-count usage (default form nets to zero -> deadlock).
__device__ __forceinline__ void cp_arrive_noinc(uint32_t addr) {
    asm volatile("cp.async.mbarrier.arrive.noinc.shared.b64 [%0];" :: "r"(addr) : "memory");
}
__device__ __forceinline__ void mbar_wait(uint32_t addr, uint32_t parity) {
    asm volatile(
        "{\n\t.reg .pred P;\n\t"
        "WL%=:\n\t"
        "mbarrier.try_wait.parity.acquire.cta.shared::cta.b64 P, [%0], %1, 0x989680;\n\t"
        "@P bra WD%=;\n\t"
        "bra WL%=;\n\t"
        "WD%=:\n\t}"
        :: "r"(addr), "r"(parity) : "memory");
}
__device__ __forceinline__ void mma_tf32(float (&c)[4],
    uint32_t a0, uint32_t a1, uint32_t a2, uint32_t a3, uint32_t b0, uint32_t b1)
{
    asm volatile(
        "mma.sync.aligned.m16n8k8.row.col.f32.tf32.tf32.f32 "
        "{%0,%1,%2,%3}, {%4,%5,%6,%7}, {%8,%9}, {%0,%1,%2,%3};"
        : "+f"(c[0]), "+f"(c[1]), "+f"(c[2]), "+f"(c[3])
        : "r"(a0), "r"(a1), "r"(a2), "r"(a3), "r"(b0), "r"(b1));
}
// ldmatrix.x4 on b16 rows == tf32 m16n8k8 A fragment (validated R7)
__device__ __forceinline__ void ldsm4(uint32_t (&r)[4], uint32_t addr) {
    asm volatile("ldmatrix.sync.aligned.m8n8.x4.shared.b16 {%0,%1,%2,%3}, [%4];"
                 : "=r"(r[0]), "=r"(r[1]), "=r"(r[2]), "=r"(r[3]) : "r"(addr));
}

// ---- pre-pass: round fp32 -> tf32-representable fp32 (vectorized) ----
__global__ __launch_bounds__(256) void k_conv(const float4* __restrict__ src,
                                              float4* __restrict__ dst, int n4)
{
    int i = blockIdx.x * 256 + threadIdx.x;
    if (i < n4) {
        float4 v = src[i];
        float4 o;
        o.x = __uint_as_float(f2tf32(v.x));
        o.y = __uint_as_float(f2tf32(v.y));
        o.z = __uint_as_float(f2tf32(v.z));
        o.w = __uint_as_float(f2tf32(v.w));
        dst[i] = o;
    }
}

// ---- fragment load for one k8-step s (0..7) ----
__device__ __forceinline__ void load_frags(uint32_t sA, const char* sB,
    int s, int wc, int g, int t4, uint32_t (&a)[4][4], uint32_t (&b)[8][2])
{
#pragma unroll
    for (int mf = 0; mf < 4; mf++)
        ldsm4(a[mf], sA + mf * 16 * A_ROW + s * 32);
    const char* pb = sB + (s * 8 + t4) * B_ROW + (wc * 64 + g) * 4;
#pragma unroll
    for (int nf = 0; nf < 8; nf++) {
        b[nf][0] = *(const uint32_t*)(pb + nf * 32);
        b[nf][1] = *(const uint32_t*)(pb + nf * 32 + 4 * B_ROW);
    }
}
__device__ __forceinline__ void mma_step(const uint32_t (&a)[4][4],
    const uint32_t (&b)[8][2], float (&acc)[4][8][4])
{
#pragma unroll
    for (int mf = 0; mf < 4; mf++)
#pragma unroll
        for (int nf = 0; nf < 8; nf++)
            mma_tf32(acc[mf][nf], a[mf][0], a[mf][1], a[mf][2], a[mf][3],
                     b[nf][0], b[nf][1]);
}

// ---- cp.async copy of one BK=64 slab (256 threads; 24 x 16B per thread) ----
struct Copier { const float *ga0, *gb0; uint32_t sa0, sb0; int lda, ldb; };
__device__ __forceinline__ void init_copier(Copier& c, uint32_t smem_u32,
    const float* __restrict__ A, int lda, const float* __restrict__ B, int ldb)
{
    const int tid = threadIdx.x;
    c.lda = lda; c.ldb = ldb;
    int m = tid >> 4, kq = tid & 15;           // A chunk j: rows m + 16j
    c.sa0 = smem_u32 + OFF_A + m * A_ROW + kq * 16;
    c.ga0 = A + (size_t)m * lda + kq * 4;
    int k = tid >> 6, nq = tid & 63;           // B chunk j: k-rows k + 4j
    c.sb0 = smem_u32 + OFF_B + k * B_ROW + nq * 16;
    c.gb0 = B + (size_t)k * ldb + nq * 4;
}
__device__ __forceinline__ void issue_slab(const Copier& c, int i) {
    const int slot = i & 1;
    const size_t ka = (size_t)i * BK;
#pragma unroll
    for (int j = 0; j < 8; j++)                // A: 2048 chunks / 256 thr
        cp16(c.sa0 + slot * A_ST + j * 16 * A_ROW, c.ga0 + ka + (size_t)j * 16 * c.lda);
#pragma unroll
    for (int j = 0; j < 16; j++)               // B: 4096 chunks / 256 thr
        cp16(c.sb0 + slot * B_ST + j * 4 * B_ROW, c.gb0 + (ka + 4 * j) * (size_t)c.ldb);
}

__device__ __forceinline__ void run_gemm(
    const float* __restrict__ A, int lda, const float* __restrict__ B, int ldb,
    int nslab, char* smem, uint32_t smem_u32, float (&acc)[4][8][4])
{
    const int tid = threadIdx.x, lane = tid & 31, wid = tid >> 5;
    const int wr = wid >> 2, wc = wid & 3, g = lane >> 2, t4 = lane & 3;

    const uint32_t sA_lane0 = smem_u32 + OFF_A
        + (uint32_t)(wr * 64 + (lane & 7) + 8 * ((lane >> 3) & 1)) * A_ROW
        + (uint32_t)(lane >> 4) * 16;

    // mbarriers: fill[2] then read[2], all expecting 256 arrivals per phase
    const uint32_t mb_fill = smem_u32 + OFF_MBAR;
    const uint32_t mb_read = smem_u32 + OFF_MBAR + 16;
    if (tid == 0) {
        mbar_init(mb_fill,      NTHR); mbar_init(mb_fill + 8, NTHR);
        mbar_init(mb_read,      NTHR); mbar_init(mb_read + 8, NTHR);
    }
    __syncthreads();

    Copier c; init_copier(c, smem_u32, A, lda, B, ldb);

    issue_slab(c, 0); cp_arrive_noinc(mb_fill);
    issue_slab(c, 1); cp_arrive_noinc(mb_fill + 8);

    for (int i = 0; i < nslab; i++) {
        const int slot = i & 1;
        const uint32_t par = (uint32_t)((i >> 1) & 1);   // phase of this slot's use
        const uint32_t sA = sA_lane0 + slot * A_ST;
        const char* sB = smem + OFF_B + slot * B_ST;

        mbar_wait(mb_fill + slot * 8, par);      // slab i landed + visible

        uint32_t a0[4][4], b0[8][2], a1[4][4], b1[8][2];
        load_frags(sA, sB, 0, wc, g, t4, a0, b0);
        load_frags(sA, sB, 1, wc, g, t4, a1, b1);
#pragma unroll
        for (int s = 0; s < 6; s += 2) {
            mma_step(a0, b0, acc);
            load_frags(sA, sB, s + 2, wc, g, t4, a0, b0);
            mma_step(a1, b1, acc);
            load_frags(sA, sB, s + 3, wc, g, t4, a1, b1);
        }
        mbar_arrive(mb_read + slot * 8);         // all reads of slot(i) issued (arrive early)
        mma_step(a0, b0, acc);                   // queued MMA covers the join below
        if (i + 2 < nslab) {
            mbar_wait(mb_read + slot * 8, par);  // all warps done reading slot; refill it
            issue_slab(c, i + 2);
            cp_arrive_noinc(mb_fill + slot * 8);
        }
        mma_step(a1, b1, acc);
    }
}

// ================= Stage 1: gu = hs @ gup[e] + gub; GLU; fold routing -> g_inter =================
__global__ __launch_bounds__(NTHR, 1) void k_gemm1(
    const float* __restrict__ routing, const float* __restrict__ gub)
{
    extern __shared__ char smem[];
    const uint32_t sb = cvta_smem(smem);
    const int tid = threadIdx.x, lane = tid & 31, wid = tid >> 5;
    const int wr = wid >> 2, wc = wid & 3, g = lane >> 2, t4 = lane & 3;
    const int e = blockIdx.z, t0 = blockIdx.y * BM, j0 = blockIdx.x * BN;

    float* rs   = (float*)(smem + OFF_AUX);        // [128]
    float* bias = (float*)(smem + OFF_AUX + 512);  // [256]
    if (tid < 128) rs[tid] = routing[(size_t)(t0 + tid) * E_NUM + e];
    bias[tid] = gub[(size_t)e * GU_COLS + j0 + tid];
    // (visibility of rs/bias to all warps is covered by the __syncthreads inside run_gemm)

    float acc[4][8][4] = {};
    run_gemm(g_hs + (size_t)t0 * H_DIM, H_DIM,
             g_w1 + (size_t)e * H_DIM * GU_COLS + j0, GU_COLS,
             H_DIM / BK, smem, sb, acc);

#pragma unroll
    for (int mf = 0; mf < 4; mf++) {
#pragma unroll
        for (int hi = 0; hi < 2; hi++) {
            const int r = wr * 64 + mf * 16 + g + hi * 8;
            const float rv = rs[r];
            float* grow = g_inter + (size_t)(t0 + r) * KQ + (size_t)e * I_DIM + (j0 >> 1);
#pragma unroll
            for (int nf = 0; nf < 8; nf++) {
                const int cn = wc * 64 + nf * 8 + 2 * t4;  // even gu col = gate; +1 = up
                float gate = acc[mf][nf][hi * 2]     + bias[cn];
                float up   = acc[mf][nf][hi * 2 + 1] + bias[cn + 1];
                gate = fminf(gate, 7.0f);
                up   = fminf(fmaxf(up, -7.0f), 7.0f);
                const float glu = gate / (1.0f + __expf(-1.702f * gate));
                grow[cn >> 1] = __uint_as_float(f2tf32((up + 1.0f) * glu * rv));
            }
        }
    }
}

// ================= Stage 2: out = inter'[T,E*I] @ down[E*I,H] + routing @ dpb =================
__global__ __launch_bounds__(NTHR, 1) void k_gemm2(
    const float* __restrict__ routing, const float* __restrict__ dpb,
    float* __restrict__ out)
{
    extern __shared__ char smem[];
    const uint32_t sb = cvta_smem(smem);
    const int tid = threadIdx.x, lane = tid & 31, wid = tid >> 5;
    const int wr = wid >> 2, wc = wid & 3, g = lane >> 2, t4 = lane & 3;
    const int t0 = blockIdx.y * BM, h0 = blockIdx.x * BN;

    float* rsm = (float*)(smem + OFF_AUX);         // [128][8]
    float* dsm = (float*)(smem + OFF_AUX + 4096);  // [8][256]
#pragma unroll
    for (int j = 0; j < 4; j++) {
        int idx = tid + NTHR * j;
        rsm[idx] = routing[(size_t)t0 * E_NUM + idx];
    }
#pragma unroll
    for (int j = 0; j < 8; j++) {
        int idx = tid + NTHR * j;
        dsm[idx] = dpb[(size_t)(idx >> 8) * H_DIM + h0 + (idx & 255)];
    }

    float acc[4][8][4] = {};
    run_gemm(g_inter + (size_t)t0 * KQ, KQ,
             g_w2 + h0, H_DIM,
             KQ / BK, smem, sb, acc);

#pragma unroll
    for (int nf = 0; nf < 8; nf++) {
        const int cn = wc * 64 + nf * 8 + 2 * t4;
        float d0[8], d1[8];
#pragma unroll
        for (int e2 = 0; e2 < 8; e2++) {
            d0[e2] = dsm[e2 * 256 + cn];
            d1[e2] = dsm[e2 * 256 + cn + 1];
        }
#pragma unroll
        for (int mf = 0; mf < 4; mf++) {
#pragma unroll
            for (int hi = 0; hi < 2; hi++) {
                const int r = wr * 64 + mf * 16 + g + hi * 8;
                const float4* rp = (const float4*)(rsm + r * 8);
                const float4 rA = rp[0], rB = rp[1];
                float b0 = rA.x * d0[0] + rA.y * d0[1] + rA.z * d0[2] + rA.w * d0[3]
                         + rB.x * d0[4] + rB.y * d0[5] + rB.z * d0[6] + rB.w * d0[7];
                float b1 = rA.x * d1[0] + rA.y * d1[1] + rA.z * d1[2] + rA.w * d1[3]
                         + rB.x * d1[4] + rB.y * d1[5] + rB.z * d1[6] + rB.w * d1[7];
                float2 v;
                v.x = acc[mf][nf][hi * 2]     + b0;
                v.y = acc[mf][nf][hi * 2 + 1] + b1;
                *(float2*)(out + (size_t)(t0 + r) * H_DIM + h0 + cn) = v;
            }
        }
    }
}

extern "C" void kernel_launch(void* const* d_in, const int* in_sizes, int n_in,
                              void* d_out, int out_size)
{
    const float* hidden  = (const float*)d_in[0];
    const float* routing = (const float*)d_in[1];
    const float* gup     = (const float*)d_in[2];
    const float* gub     = (const float*)d_in[3];
    const float* down    = (const float*)d_in[4];
    const float* dpb     = (const float*)d_in[5];
    float* out = (float*)d_out;

    cudaFuncSetAttribute(k_gemm1, cudaFuncAttributeMaxDynamicSharedMemorySize, SMEM_SZ);
    cudaFuncSetAttribute(k_gemm2, cudaFuncAttributeMaxDynamicSharedMemorySize, SMEM_SZ);

    float *w1, *w2, *hs;
    cudaGetSymbolAddress((void**)&w1, g_w1);
    cudaGetSymbolAddress((void**)&w2, g_w2);
    cudaGetSymbolAddress((void**)&hs, g_hs);

    // pre-round all GEMM operands to tf32-representable fp32 (removes in-loop CVT)
    k_conv<<<(16777216 + 255) / 256, 256>>>((const float4*)gup,    (float4*)w1, 16777216);
    k_conv<<<( 8388608 + 255) / 256, 256>>>((const float4*)down,   (float4*)w2,  8388608);
    k_conv<<<( 1048576 + 255) / 256, 256>>>((const float4*)hidden, (float4*)hs,  1048576);

    dim3 g1(GU_COLS / BN, T_DIM / BM, E_NUM);   // (16, 16, 8)
    k_gemm1<<<g1, NTHR, SMEM_SZ>>>(routing, gub);

    dim3 g2(H_DIM / BN, T_DIM / BM);            // (8, 16)
    k_gemm2<<<g2, NTHR, SMEM_SZ>>>(routing, dpb, out);
}